// round 1
// baseline (speedup 1.0000x reference)
#include <cuda_runtime.h>

// CrossNet: y_{k+1} = y_k * (y_k . w_k + 1) + b_k, 3 layers fused.
// B=16384 rows, D=2048 cols, fp32.
// One CTA per row; row lives in registers (1 float4 per thread, 512 threads).
// Weights/biases loaded once per CTA into registers (L2-resident).

#define D 2048
#define VEC (D / 4)          // 512 float4 per row
#define THREADS 512
#define NWARP (THREADS / 32)

__global__ __launch_bounds__(THREADS, 4)
void crossnet_kernel(const float4* __restrict__ x,
                     const float4* __restrict__ w1, const float4* __restrict__ b1,
                     const float4* __restrict__ w2, const float4* __restrict__ b2,
                     const float4* __restrict__ w3, const float4* __restrict__ b3,
                     float4* __restrict__ out)
{
    __shared__ float sh[NWARP];
    __shared__ float sh_s;

    const int t    = threadIdx.x;          // column slice index 0..511
    const int lane = t & 31;
    const int wid  = t >> 5;
    const long long idx = (long long)blockIdx.x * VEC + t;

    // Row data
    float4 y = x[idx];

    // Per-column weights/biases, row-invariant (L2 hit after first wave)
    const float4 wv1 = __ldg(&w1[t]);
    const float4 bv1 = __ldg(&b1[t]);
    const float4 wv2 = __ldg(&w2[t]);
    const float4 bv2 = __ldg(&b2[t]);
    const float4 wv3 = __ldg(&w3[t]);
    const float4 bv3 = __ldg(&b3[t]);

    #pragma unroll
    for (int layer = 0; layer < 3; ++layer) {
        const float4 wv = (layer == 0) ? wv1 : (layer == 1) ? wv2 : wv3;
        const float4 bv = (layer == 0) ? bv1 : (layer == 1) ? bv2 : bv3;

        // partial dot
        float p = y.x * wv.x + y.y * wv.y + y.z * wv.z + y.w * wv.w;

        // warp reduce
        #pragma unroll
        for (int off = 16; off > 0; off >>= 1)
            p += __shfl_xor_sync(0xFFFFFFFFu, p, off);

        if (lane == 0) sh[wid] = p;
        __syncthreads();

        if (wid == 0) {
            float v = (lane < NWARP) ? sh[lane] : 0.0f;
            #pragma unroll
            for (int off = 8; off > 0; off >>= 1)
                v += __shfl_xor_sync(0xFFFFFFFFu, v, off);
            if (lane == 0) sh_s = v;
        }
        __syncthreads();

        const float s1 = sh_s + 1.0f;   // y*(s) + b + y == y*(s+1) + b

        y.x = fmaf(y.x, s1, bv.x);
        y.y = fmaf(y.y, s1, bv.y);
        y.z = fmaf(y.z, s1, bv.z);
        y.w = fmaf(y.w, s1, bv.w);

        // sh_s is re-written next layer; the __syncthreads at the top of the
        // next reduction (after sh[wid] write) would race with sh_s read,
        // so we need a barrier before sh is overwritten. The sh[wid] write
        // happens after every thread has read sh_s? No: warp divergence.
        // Be safe:
        if (layer < 2) __syncthreads();
    }

    out[idx] = y;
}

extern "C" void kernel_launch(void* const* d_in, const int* in_sizes, int n_in,
                              void* d_out, int out_size)
{
    const float4* x  = (const float4*)d_in[0];
    const float4* w1 = (const float4*)d_in[1];
    const float4* b1 = (const float4*)d_in[2];
    const float4* w2 = (const float4*)d_in[3];
    const float4* b2 = (const float4*)d_in[4];
    const float4* w3 = (const float4*)d_in[5];
    const float4* b3 = (const float4*)d_in[6];
    float4* out = (float4*)d_out;

    const int B = in_sizes[0] / D;   // 16384
    crossnet_kernel<<<B, THREADS>>>(x, w1, b1, w2, b2, w3, b3, out);
}

// round 2
// speedup vs baseline: 1.3136x; 1.3136x over previous
#include <cuda_runtime.h>

// CrossNet: y_{k+1} = y_k * (y_k . w_k + 1) + b_k, 3 fused layers.
// B=16384 rows, D=2048 cols, fp32.
// R=4 rows per CTA: amortizes w/b loads and reduction barriers 4x,
// and gives each thread 4 independent DRAM loads (MLP=4).

#define D 2048
#define VEC (D / 4)          // 512 float4 per row
#define THREADS 512
#define NWARP (THREADS / 32) // 16
#define R 4                  // rows per CTA

__global__ __launch_bounds__(THREADS, 2)
void crossnet_kernel(const float4* __restrict__ x,
                     const float4* __restrict__ w1, const float4* __restrict__ b1,
                     const float4* __restrict__ w2, const float4* __restrict__ b2,
                     const float4* __restrict__ w3, const float4* __restrict__ b3,
                     float4* __restrict__ out)
{
    __shared__ float4 sh[NWARP];   // per-warp partials, one component per row
    __shared__ float  sh_s[R];     // broadcast: per-row dot result

    const int t    = threadIdx.x;          // column slice 0..511
    const int lane = t & 31;
    const int wid  = t >> 5;
    const long long base = (long long)blockIdx.x * (R * VEC) + t;

    // 4 independent row loads (streaming: no reuse, keep L2 for w/b)
    float4 y[R];
    #pragma unroll
    for (int r = 0; r < R; ++r)
        y[r] = __ldcs(&x[base + (long long)r * VEC]);

    // Per-column weights/biases, row-invariant (L2/L1 resident)
    const float4 wv1 = __ldg(&w1[t]);
    const float4 bv1 = __ldg(&b1[t]);
    const float4 wv2 = __ldg(&w2[t]);
    const float4 bv2 = __ldg(&b2[t]);
    const float4 wv3 = __ldg(&w3[t]);
    const float4 bv3 = __ldg(&b3[t]);

    #pragma unroll
    for (int layer = 0; layer < 3; ++layer) {
        const float4 wv = (layer == 0) ? wv1 : (layer == 1) ? wv2 : wv3;
        const float4 bv = (layer == 0) ? bv1 : (layer == 1) ? bv2 : bv3;

        // partial dot per row
        float p[R];
        #pragma unroll
        for (int r = 0; r < R; ++r)
            p[r] = y[r].x * wv.x + y[r].y * wv.y + y[r].z * wv.z + y[r].w * wv.w;

        // warp butterfly reduce, all 4 rows together
        #pragma unroll
        for (int off = 16; off > 0; off >>= 1) {
            #pragma unroll
            for (int r = 0; r < R; ++r)
                p[r] += __shfl_xor_sync(0xFFFFFFFFu, p[r], off);
        }

        if (lane == 0) sh[wid] = make_float4(p[0], p[1], p[2], p[3]);
        __syncthreads();

        if (wid == 0) {
            float4 v = (lane < NWARP) ? sh[lane]
                                      : make_float4(0.f, 0.f, 0.f, 0.f);
            #pragma unroll
            for (int off = 8; off > 0; off >>= 1) {
                v.x += __shfl_xor_sync(0xFFFFFFFFu, v.x, off);
                v.y += __shfl_xor_sync(0xFFFFFFFFu, v.y, off);
                v.z += __shfl_xor_sync(0xFFFFFFFFu, v.z, off);
                v.w += __shfl_xor_sync(0xFFFFFFFFu, v.w, off);
            }
            if (lane == 0) {
                sh_s[0] = v.x; sh_s[1] = v.y; sh_s[2] = v.z; sh_s[3] = v.w;
            }
        }
        __syncthreads();

        // y = y * (s + 1) + b   (== y*s + b + y)
        float s[R];
        #pragma unroll
        for (int r = 0; r < R; ++r) s[r] = sh_s[r] + 1.0f;

        #pragma unroll
        for (int r = 0; r < R; ++r) {
            y[r].x = fmaf(y[r].x, s[r], bv.x);
            y[r].y = fmaf(y[r].y, s[r], bv.y);
            y[r].z = fmaf(y[r].z, s[r], bv.z);
            y[r].w = fmaf(y[r].w, s[r], bv.w);
        }

        // protect sh/sh_s from next layer's overwrite
        if (layer < 2) __syncthreads();
    }

    #pragma unroll
    for (int r = 0; r < R; ++r)
        __stcs(&out[base + (long long)r * VEC], y[r]);
}

extern "C" void kernel_launch(void* const* d_in, const int* in_sizes, int n_in,
                              void* d_out, int out_size)
{
    const float4* x  = (const float4*)d_in[0];
    const float4* w1 = (const float4*)d_in[1];
    const float4* b1 = (const float4*)d_in[2];
    const float4* w2 = (const float4*)d_in[3];
    const float4* b2 = (const float4*)d_in[4];
    const float4* w3 = (const float4*)d_in[5];
    const float4* b3 = (const float4*)d_in[6];
    float4* out = (float4*)d_out;

    const int B = in_sizes[0] / D;   // 16384
    crossnet_kernel<<<B / R, THREADS>>>(x, w1, b1, w2, b2, w3, b3, out);
}